// round 8
// baseline (speedup 1.0000x reference)
#include <cuda_runtime.h>
#include <stdint.h>

// BallPointQuery: B=4, N=16384, M=2048, MAX_SAMPLES=64, RADIUS=0.2
// pcs float32 [B,N,3]; centroids float32 [B,M,3]
// Output buffer: 524288 x 4 bytes, compared as float32 (indices stored as floats).
//   - int64 writes faulted (buffer is 2 MB)  [R4/R5]
//   - int32 writes gave rel_err == 1.0 exactly (denormal reinterpretation) [R6/R7]

#define BQ_B 4
#define BQ_N 16384
#define BQ_M 2048
#define BQ_S 64

__global__ __launch_bounds__(256)
void ball_query_kernel(const float* __restrict__ pcs,
                       const float* __restrict__ cents,
                       float* __restrict__ out)
{
    const int warp_global = (blockIdx.x * blockDim.x + threadIdx.x) >> 5;
    const int lane = threadIdx.x & 31;
    if (warp_global >= BQ_B * BQ_M) return;

    const int b = warp_global / BQ_M;
    const int m = warp_global % BQ_M;

    const int cbase = (b * BQ_M + m) * 3;
    const float cx = cents[cbase + 0];
    const float cy = cents[cbase + 1];
    const float cz = cents[cbase + 2];

    // c2 = cx*cx + cy*cy + cz*cz, no fma contraction (match XLA expanded form)
    const float c2 = __fadd_rn(__fadd_rn(__fmul_rn(cx, cx), __fmul_rn(cy, cy)),
                               __fmul_rn(cz, cz));
    // r2 exactly as reference: float32(0.2 * 0.2) computed in double
    const float r2 = (float)(0.2 * 0.2);

    const float* __restrict__ pc = pcs + b * BQ_N * 3;
    float* __restrict__ o = out + (b * BQ_M + m) * BQ_S;

    int count = 0;
    int first = BQ_N;  // reference yields N when no point is in range

    for (int base = 0; base < BQ_N; base += 32) {
        const int n = base + lane;
        const float px = pc[n * 3 + 0];
        const float py = pc[n * 3 + 1];
        const float pz = pc[n * 3 + 2];

        const float p2 = __fadd_rn(__fadd_rn(__fmul_rn(px, px), __fmul_rn(py, py)),
                                   __fmul_rn(pz, pz));
        const float cross = __fadd_rn(__fadd_rn(__fmul_rn(cx, px), __fmul_rn(cy, py)),
                                      __fmul_rn(cz, pz));
        // d2 = (c2 + p2) - 2*cross
        const float d2 = __fsub_rn(__fadd_rn(c2, p2), __fmul_rn(2.0f, cross));

        const unsigned mask = __ballot_sync(0xffffffffu, d2 <= r2);
        if (mask) {
            if (count == 0) first = base + (__ffs(mask) - 1);
            if (d2 <= r2) {
                const int slot = count + __popc(mask & ((1u << lane) - 1u));
                if (slot < BQ_S) o[slot] = (float)n;   // index as float32
            }
            count += __popc(mask);
            if (count >= BQ_S) break;
        }
    }

    // Pad remaining slots with the first found index (or N if none found).
    const float padv = (float)first;
    #pragma unroll
    for (int s = lane; s < BQ_S; s += 32) {
        if (s >= count) o[s] = padv;
    }
}

extern "C" void kernel_launch(void* const* d_in, const int* in_sizes, int n_in,
                              void* d_out, int out_size)
{
    // Bind by RELATIVE size: pcs is 8x larger than centroids under any unit
    // convention (elements or bytes), any input order. Pick the two largest
    // buffers; the bigger one is pcs.
    int pi = 0, ci = (n_in > 1) ? 1 : 0;
    if (n_in >= 2) {
        int i0 = 0;
        for (int i = 1; i < n_in; i++)
            if (in_sizes[i] > in_sizes[i0]) i0 = i;
        int i1 = (i0 == 0) ? 1 : 0;
        for (int i = 0; i < n_in; i++)
            if (i != i0 && in_sizes[i] > in_sizes[i1]) i1 = i;
        pi = i0;
        ci = i1;
    }
    const float* pcs   = (const float*)d_in[pi];
    const float* cents = (const float*)d_in[ci];
    float* out = (float*)d_out;

    const int total_warps = BQ_B * BQ_M;           // 8192
    const int threads = 256;                        // 8 warps per block
    const int blocks = (total_warps * 32 + threads - 1) / threads;  // 1024
    ball_query_kernel<<<blocks, threads>>>(pcs, cents, out);
}

// round 9
// speedup vs baseline: 1.7582x; 1.7582x over previous
#include <cuda_runtime.h>
#include <stdint.h>

// BallPointQuery: B=4, N=16384, M=2048, MAX_SAMPLES=64, RADIUS=0.2
// pcs float32 [B,N,3]; centroids float32 [B,M,3]
// Output: float32 [B,M,64] (indices stored as floats; established R8).

#define BQ_B 4
#define BQ_N 16384
#define BQ_M 2048
#define BQ_S 64

// Packed points: (px, py, pz, p2) — allocation-free scratch.
__device__ float4 g_pack[BQ_B * BQ_N];

__global__ __launch_bounds__(256)
void pack_kernel(const float* __restrict__ pcs)
{
    const int i = blockIdx.x * blockDim.x + threadIdx.x;
    if (i >= BQ_B * BQ_N) return;
    const float px = pcs[i * 3 + 0];
    const float py = pcs[i * 3 + 1];
    const float pz = pcs[i * 3 + 2];
    // p2 with the exact same non-fused sequence as the reference
    const float p2 = __fadd_rn(__fadd_rn(__fmul_rn(px, px), __fmul_rn(py, py)),
                               __fmul_rn(pz, pz));
    g_pack[i] = make_float4(px, py, pz, p2);
}

__global__ __launch_bounds__(64)
void ball_query_kernel(const float* __restrict__ cents,
                       float* __restrict__ out)
{
    const int warp_global = (blockIdx.x * blockDim.x + threadIdx.x) >> 5;
    const int lane = threadIdx.x & 31;
    if (warp_global >= BQ_B * BQ_M) return;

    const int b = warp_global / BQ_M;
    const int m = warp_global % BQ_M;

    const int cbase = (b * BQ_M + m) * 3;
    const float cx = cents[cbase + 0];
    const float cy = cents[cbase + 1];
    const float cz = cents[cbase + 2];

    const float c2 = __fadd_rn(__fadd_rn(__fmul_rn(cx, cx), __fmul_rn(cy, cy)),
                               __fmul_rn(cz, cz));
    const float r2 = (float)(0.2 * 0.2);

    const float4* __restrict__ pc4 = g_pack + b * BQ_N;
    float* __restrict__ o = out + (b * BQ_M + m) * BQ_S;

    int count = 0;
    int first = BQ_N;

    // Software-pipelined: loads for the next 64-point chunk issue before the
    // current chunk's ballots, hiding memory latency behind warp collectives.
    float4 a0 = pc4[lane];
    float4 a1 = pc4[32 + lane];

    for (int base = 0; base < BQ_N; base += 64) {
        float4 n0, n1;
        const int nb = base + 64;
        if (nb < BQ_N) {               // prefetch next chunk (warp-uniform branch)
            n0 = pc4[nb + lane];
            n1 = pc4[nb + 32 + lane];
        }

        // d2 = (c2 + p2) - 2*cross, reference-exact rounding
        const float cr0 = __fadd_rn(__fadd_rn(__fmul_rn(cx, a0.x), __fmul_rn(cy, a0.y)),
                                    __fmul_rn(cz, a0.z));
        const float d20 = __fsub_rn(__fadd_rn(c2, a0.w), __fmul_rn(2.0f, cr0));
        const float cr1 = __fadd_rn(__fadd_rn(__fmul_rn(cx, a1.x), __fmul_rn(cy, a1.y)),
                                    __fmul_rn(cz, a1.z));
        const float d21 = __fsub_rn(__fadd_rn(c2, a1.w), __fmul_rn(2.0f, cr1));

        const bool h0 = (d20 <= r2);
        const bool h1 = (d21 <= r2);
        const unsigned m0 = __ballot_sync(0xffffffffu, h0);
        const unsigned m1 = __ballot_sync(0xffffffffu, h1);

        if (m0 | m1) {
            if (count == 0)
                first = m0 ? (base + (__ffs(m0) - 1)) : (base + 32 + (__ffs(m1) - 1));

            const unsigned below = (1u << lane) - 1u;
            if (h0) {
                const int slot = count + __popc(m0 & below);
                if (slot < BQ_S) o[slot] = (float)(base + lane);
            }
            const int c1 = count + __popc(m0);
            if (h1) {
                const int slot = c1 + __popc(m1 & below);
                if (slot < BQ_S) o[slot] = (float)(base + 32 + lane);
            }
            count = c1 + __popc(m1);
            if (count >= BQ_S) break;
        }

        a0 = n0;
        a1 = n1;
    }

    const float padv = (float)first;
    #pragma unroll
    for (int s = lane; s < BQ_S; s += 32) {
        if (s >= count) o[s] = padv;
    }
}

extern "C" void kernel_launch(void* const* d_in, const int* in_sizes, int n_in,
                              void* d_out, int out_size)
{
    // Bind by RELATIVE size: pcs is the largest buffer under any unit
    // convention; centroids the second largest.
    int pi = 0, ci = (n_in > 1) ? 1 : 0;
    if (n_in >= 2) {
        int i0 = 0;
        for (int i = 1; i < n_in; i++)
            if (in_sizes[i] > in_sizes[i0]) i0 = i;
        int i1 = (i0 == 0) ? 1 : 0;
        for (int i = 0; i < n_in; i++)
            if (i != i0 && in_sizes[i] > in_sizes[i1]) i1 = i;
        pi = i0;
        ci = i1;
    }
    const float* pcs   = (const float*)d_in[pi];
    const float* cents = (const float*)d_in[ci];
    float* out = (float*)d_out;

    const int npts = BQ_B * BQ_N;
    pack_kernel<<<(npts + 255) / 256, 256>>>(pcs);

    const int total_warps = BQ_B * BQ_M;            // 8192
    const int threads = 64;                          // 2 warps/block
    const int blocks = (total_warps * 32 + threads - 1) / threads;  // 4096
    ball_query_kernel<<<blocks, threads>>>(cents, out);
}